// round 14
// baseline (speedup 1.0000x reference)
#include <cuda_runtime.h>
#include <cuda_fp16.h>
#include <mma.h>
#include <cstdint>

using namespace nvcuda;

// GraphConvolution: y = A @ (x @ W^T) + b
//   x: (B=4, N=50000, C=128) f32, adj: (2, E=800000) i32, vals: (E,) f32
//   W: (128,128) f32, b: (128,) f32, out: (B,N,128) f32

#define C_DIM 128
#define B_DIM 4
#define N_ROWS 50000
#define E_MAX  800000

// z stored fp16, node-major: z_h[n][b][c] -> 128 uint2 (512 halfs) per node.
__device__ uint2  g_zh[(size_t)N_ROWS * 128];
__device__ int    g_cnt[N_ROWS];
__device__ int    g_rowptr[N_ROWS + 1];
__device__ int    g_ofs[N_ROWS];
__device__ float2 g_edata[E_MAX];

// ===========================================================================
// GEMM z = x @ W^T via wmma fp16 (m16n16k16), fp32 accumulate,
// output fp16 node-major. (exact R13 version — known-good ~25us)
// ===========================================================================
#define LDAH 136
#define LDO  132
#define GEMM_SMEM (2 * 128 * LDAH * (int)sizeof(__half))   // 69632 bytes

__global__ __launch_bounds__(256, 2)
void gemm_wmma(const float* __restrict__ x, const float* __restrict__ W,
               int M, int N) {
    extern __shared__ char smemraw[];
    __half* As = (__half*)smemraw;            // [128][LDAH]
    __half* Bs = As + 128 * LDAH;             // [128][LDAH]

    const int tid = threadIdx.x;
    const int wid = tid >> 5;
    const long long m0 = (long long)blockIdx.x * 128;

    #pragma unroll
    for (int it = 0; it < 16; it++) {
        int idx = tid + it * 256;
        int row = idx >> 5;
        int kq  = idx & 31;
        long long gm = m0 + row; if (gm >= M) gm = M - 1;
        float4 v = __ldcs((const float4*)(x + gm * C_DIM + kq * 4));
        __half2 h0 = __floats2half2_rn(v.x, v.y);
        __half2 h1 = __floats2half2_rn(v.z, v.w);
        uint2 p;
        p.x = *(uint32_t*)&h0;
        p.y = *(uint32_t*)&h1;
        *(uint2*)(As + row * LDAH + kq * 4) = p;
    }
    #pragma unroll
    for (int it = 0; it < 16; it++) {
        int idx = tid + it * 256;
        int row = idx >> 5;
        int kq  = idx & 31;
        float4 v = *(const float4*)(W + row * C_DIM + kq * 4);
        __half2 h0 = __floats2half2_rn(v.x, v.y);
        __half2 h1 = __floats2half2_rn(v.z, v.w);
        uint2 p;
        p.x = *(uint32_t*)&h0;
        p.y = *(uint32_t*)&h1;
        *(uint2*)(Bs + row * LDAH + kq * 4) = p;
    }
    __syncthreads();

    const int wm = wid & 1;
    const int wn = wid >> 1;

    wmma::fragment<wmma::accumulator, 16, 16, 16, float> acc[4][2];
    #pragma unroll
    for (int i = 0; i < 4; i++)
        #pragma unroll
        for (int j = 0; j < 2; j++) wmma::fill_fragment(acc[i][j], 0.0f);

    #pragma unroll
    for (int ks = 0; ks < 8; ks++) {
        const int k = ks * 16;
        wmma::fragment<wmma::matrix_a, 16, 16, 16, __half, wmma::row_major> a[4];
        wmma::fragment<wmma::matrix_b, 16, 16, 16, __half, wmma::col_major> b[2];
        #pragma unroll
        for (int i = 0; i < 4; i++)
            wmma::load_matrix_sync(a[i], As + (wm * 64 + i * 16) * LDAH + k, LDAH);
        #pragma unroll
        for (int j = 0; j < 2; j++)
            wmma::load_matrix_sync(b[j], Bs + (wn * 32 + j * 16) * LDAH + k, LDAH);
        #pragma unroll
        for (int i = 0; i < 4; i++)
            #pragma unroll
            for (int j = 0; j < 2; j++)
                wmma::mma_sync(acc[i][j], a[i], b[j], acc[i][j]);
    }

    __syncthreads();
    float* Os = (float*)smemraw;   // 128*132*4 = 67584 <= 69632
    #pragma unroll
    for (int i = 0; i < 4; i++)
        #pragma unroll
        for (int j = 0; j < 2; j++)
            wmma::store_matrix_sync(
                Os + (wm * 64 + i * 16) * LDO + wn * 32 + j * 16,
                acc[i][j], LDO, wmma::mem_row_major);
    __syncthreads();

    #pragma unroll
    for (int it = 0; it < 16; it++) {
        int idx = tid + it * 256;
        int row = idx >> 5;
        int q   = idx & 31;
        long long gm = m0 + row;
        if (gm < M) {
            float4 v = *(const float4*)(Os + row * LDO + q * 4);
            __half2 h0 = __floats2half2_rn(v.x, v.y);
            __half2 h1 = __floats2half2_rn(v.z, v.w);
            int b = (int)(gm / N);
            int n = (int)(gm % N);
            uint2 pack;
            pack.x = *(uint32_t*)&h0;
            pack.y = *(uint32_t*)&h1;
            g_zh[(size_t)n * 128 + b * 32 + q] = pack;
        }
    }
}

// ===========================================================================
// CSR build
// ===========================================================================
__global__ void k_zero_cnt(int n) {
    int i = blockIdx.x * blockDim.x + threadIdx.x;
    if (i < n) g_cnt[i] = 0;
}

__global__ void k_count(const int* __restrict__ rows, int E) {
    int e = blockIdx.x * blockDim.x + threadIdx.x;
    if (e < E) atomicAdd(&g_cnt[rows[e]], 1);
}

#define SCAN_T 1024
__global__ __launch_bounds__(SCAN_T)
void k_scan(int n, int E) {
    __shared__ int s[SCAN_T];
    const int t = threadIdx.x;
    const int chunk = (n + SCAN_T - 1) / SCAN_T;
    const int base = t * chunk;
    int sum = 0;
    for (int j = 0; j < chunk; j++) {
        int r = base + j;
        if (r < n) sum += g_cnt[r];
    }
    s[t] = sum;
    __syncthreads();
    #pragma unroll
    for (int d = 1; d < SCAN_T; d <<= 1) {
        int v = (t >= d) ? s[t - d] : 0;
        __syncthreads();
        s[t] += v;
        __syncthreads();
    }
    int run = s[t] - sum;
    for (int j = 0; j < chunk; j++) {
        int r = base + j;
        if (r < n) {
            g_rowptr[r] = run;
            g_ofs[r]    = run;
            run += g_cnt[r];
        }
    }
    if (t == 0) g_rowptr[n] = E;
}

__global__ void k_fill(const int* __restrict__ rows, const int* __restrict__ cols,
                       const float* __restrict__ vals, int E) {
    int e = blockIdx.x * blockDim.x + threadIdx.x;
    if (e >= E) return;
    int r = rows[e];
    int pos = atomicAdd(&g_ofs[r], 1);
    float2 ed;
    ed.x = __int_as_float(cols[e]);
    ed.y = vals[e];
    g_edata[pos] = ed;
}

// ===========================================================================
// Gather: 2 warps per row (warp covers 2 batches). 4-edge straight-line
// unrolled mainloop: all records + all 8 z-block loads issued before FMAs
// (high MLP). fp32 accumulate, bias fused, streaming stores.
// ===========================================================================
__global__ __launch_bounds__(256)
void k_gather(const float* __restrict__ bias, float* __restrict__ out, int N) {
    int gw   = (blockIdx.x * blockDim.x + threadIdx.x) >> 5;
    int lane = threadIdx.x & 31;
    int r    = gw >> 1;
    int half = gw & 1;          // 0: batches {0,1}, 1: batches {2,3}
    if (r >= N) return;
    const int boff = half * 64; // uint2 offset into node block

    float4 acc0 = make_float4(0.f, 0.f, 0.f, 0.f);
    float4 acc1 = acc0, bcc0 = acc0, bcc1 = acc0;

    const int start = g_rowptr[r];
    const int end   = g_rowptr[r + 1];

    int i = start;

    // 4-edge unrolled mainloop: batch all loads, then all FMAs.
    for (; i + 4 <= end; i += 4) {
        float2 e0 = __ldg(&g_edata[i]);
        float2 e1 = __ldg(&g_edata[i + 1]);
        float2 e2 = __ldg(&g_edata[i + 2]);
        float2 e3 = __ldg(&g_edata[i + 3]);
        const uint2* s0 = g_zh + (size_t)__float_as_int(e0.x) * 128 + boff + lane;
        const uint2* s1 = g_zh + (size_t)__float_as_int(e1.x) * 128 + boff + lane;
        const uint2* s2 = g_zh + (size_t)__float_as_int(e2.x) * 128 + boff + lane;
        const uint2* s3 = g_zh + (size_t)__float_as_int(e3.x) * 128 + boff + lane;
        uint2 p0a = __ldg(s0), p0b = __ldg(s0 + 32);
        uint2 p1a = __ldg(s1), p1b = __ldg(s1 + 32);
        uint2 p2a = __ldg(s2), p2b = __ldg(s2 + 32);
        uint2 p3a = __ldg(s3), p3b = __ldg(s3 + 32);

        float2 fa, fb;
        float v;
        v = e0.y;
        fa = __half22float2(*(__half2*)&p0a.x); fb = __half22float2(*(__half2*)&p0a.y);
        acc0.x = fmaf(v, fa.x, acc0.x); acc0.y = fmaf(v, fa.y, acc0.y);
        acc0.z = fmaf(v, fb.x, acc0.z); acc0.w = fmaf(v, fb.y, acc0.w);
        fa = __half22float2(*(__half2*)&p0b.x); fb = __half22float2(*(__half2*)&p0b.y);
        acc1.x = fmaf(v, fa.x, acc1.x); acc1.y = fmaf(v, fa.y, acc1.y);
        acc1.z = fmaf(v, fb.x, acc1.z); acc1.w = fmaf(v, fb.y, acc1.w);
        v = e1.y;
        fa = __half22float2(*(__half2*)&p1a.x); fb = __half22float2(*(__half2*)&p1a.y);
        bcc0.x = fmaf(v, fa.x, bcc0.x); bcc0.y = fmaf(v, fa.y, bcc0.y);
        bcc0.z = fmaf(v, fb.x, bcc0.z); bcc0.w = fmaf(v, fb.y, bcc0.w);
        fa = __half22float2(*(__half2*)&p1b.x); fb = __half22float2(*(__half2*)&p1b.y);
        bcc1.x = fmaf(v, fa.x, bcc1.x); bcc1.y = fmaf(v, fa.y, bcc1.y);
        bcc1.z = fmaf(v, fb.x, bcc1.z); bcc1.w = fmaf(v, fb.y, bcc1.w);
        v = e2.y;
        fa = __half22float2(*(__half2*)&p2a.x); fb = __half22float2(*(__half2*)&p2a.y);
        acc0.x = fmaf(v, fa.x, acc0.x); acc0.y = fmaf(v, fa.y, acc0.y);
        acc0.z = fmaf(v, fb.x, acc0.z); acc0.w = fmaf(v, fb.y, acc0.w);
        fa = __half22float2(*(__half2*)&p2b.x); fb = __half22float2(*(__half2*)&p2b.y);
        acc1.x = fmaf(v, fa.x, acc1.x); acc1.y = fmaf(v, fa.y, acc1.y);
        acc1.z = fmaf(v, fb.x, acc1.z); acc1.w = fmaf(v, fb.y, acc1.w);
        v = e3.y;
        fa = __half22float2(*(__half2*)&p3a.x); fb = __half22float2(*(__half2*)&p3a.y);
        bcc0.x = fmaf(v, fa.x, bcc0.x); bcc0.y = fmaf(v, fa.y, bcc0.y);
        bcc0.z = fmaf(v, fb.x, bcc0.z); bcc0.w = fmaf(v, fb.y, bcc0.w);
        fa = __half22float2(*(__half2*)&p3b.x); fb = __half22float2(*(__half2*)&p3b.y);
        bcc1.x = fmaf(v, fa.x, bcc1.x); bcc1.y = fmaf(v, fa.y, bcc1.y);
        bcc1.z = fmaf(v, fb.x, bcc1.z); bcc1.w = fmaf(v, fb.y, bcc1.w);
    }

    // 2-edge step.
    for (; i + 2 <= end; i += 2) {
        float2 e0 = __ldg(&g_edata[i]);
        float2 e1 = __ldg(&g_edata[i + 1]);
        const uint2* s0 = g_zh + (size_t)__float_as_int(e0.x) * 128 + boff + lane;
        const uint2* s1 = g_zh + (size_t)__float_as_int(e1.x) * 128 + boff + lane;
        uint2 p0a = __ldg(s0), p0b = __ldg(s0 + 32);
        uint2 p1a = __ldg(s1), p1b = __ldg(s1 + 32);
        float2 fa, fb;
        float v = e0.y;
        fa = __half22float2(*(__half2*)&p0a.x); fb = __half22float2(*(__half2*)&p0a.y);
        acc0.x = fmaf(v, fa.x, acc0.x); acc0.y = fmaf(v, fa.y, acc0.y);
        acc0.z = fmaf(v, fb.x, acc0.z); acc0.w = fmaf(v, fb.y, acc0.w);
        fa = __half22float2(*(__half2*)&p0b.x); fb = __half22float2(*(__half2*)&p0b.y);
        acc1.x = fmaf(v, fa.x, acc1.x); acc1.y = fmaf(v, fa.y, acc1.y);
        acc1.z = fmaf(v, fb.x, acc1.z); acc1.w = fmaf(v, fb.y, acc1.w);
        v = e1.y;
        fa = __half22float2(*(__half2*)&p1a.x); fb = __half22float2(*(__half2*)&p1a.y);
        bcc0.x = fmaf(v, fa.x, bcc0.x); bcc0.y = fmaf(v, fa.y, bcc0.y);
        bcc0.z = fmaf(v, fb.x, bcc0.z); bcc0.w = fmaf(v, fb.y, bcc0.w);
        fa = __half22float2(*(__half2*)&p1b.x); fb = __half22float2(*(__half2*)&p1b.y);
        bcc1.x = fmaf(v, fa.x, bcc1.x); bcc1.y = fmaf(v, fa.y, bcc1.y);
        bcc1.z = fmaf(v, fb.x, bcc1.z); bcc1.w = fmaf(v, fb.y, bcc1.w);
    }

    // Final edge.
    if (i < end) {
        float2 e0 = __ldg(&g_edata[i]);
        const uint2* s0 = g_zh + (size_t)__float_as_int(e0.x) * 128 + boff + lane;
        uint2 p0a = __ldg(s0), p0b = __ldg(s0 + 32);
        float2 fa, fb;
        float v = e0.y;
        fa = __half22float2(*(__half2*)&p0a.x); fb = __half22float2(*(__half2*)&p0a.y);
        acc0.x = fmaf(v, fa.x, acc0.x); acc0.y = fmaf(v, fa.y, acc0.y);
        acc0.z = fmaf(v, fb.x, acc0.z); acc0.w = fmaf(v, fb.y, acc0.w);
        fa = __half22float2(*(__half2*)&p0b.x); fb = __half22float2(*(__half2*)&p0b.y);
        acc1.x = fmaf(v, fa.x, acc1.x); acc1.y = fmaf(v, fa.y, acc1.y);
        acc1.z = fmaf(v, fb.x, acc1.z); acc1.w = fmaf(v, fb.y, acc1.w);
    }

    float4 bv = ((const float4*)bias)[lane];
    acc0.x += bcc0.x + bv.x; acc0.y += bcc0.y + bv.y;
    acc0.z += bcc0.z + bv.z; acc0.w += bcc0.w + bv.w;
    acc1.x += bcc1.x + bv.x; acc1.y += bcc1.y + bv.y;
    acc1.z += bcc1.z + bv.z; acc1.w += bcc1.w + bv.w;

    const size_t NB = (size_t)N * 32;   // float4 units per batch
    float4* dst = (float4*)out + (size_t)(half * 2) * NB + (size_t)r * 32 + lane;
    __stcs(dst,      acc0);
    __stcs(dst + NB, acc1);
}

// ===========================================================================
extern "C" void kernel_launch(void* const* d_in, const int* in_sizes, int n_in,
                              void* d_out, int out_size) {
    const float* x    = (const float*)d_in[0];
    const int*   adj  = (const int*)d_in[1];
    const float* vals = (const float*)d_in[2];
    const float* W    = (const float*)d_in[3];
    const float* bias = (const float*)d_in[4];
    float* out = (float*)d_out;

    const int E = in_sizes[2];
    const int N = in_sizes[0] / (B_DIM * C_DIM);
    const int M = B_DIM * N;

    const int* rows = adj;
    const int* cols = adj + E;

    static cudaStream_t s2 = nullptr;
    static cudaEvent_t evFork, evJoin;
    if (!s2) {
        cudaStreamCreateWithFlags(&s2, cudaStreamNonBlocking);
        cudaEventCreateWithFlags(&evFork, cudaEventDisableTiming);
        cudaEventCreateWithFlags(&evJoin, cudaEventDisableTiming);
        cudaFuncSetAttribute(gemm_wmma,
                             cudaFuncAttributeMaxDynamicSharedMemorySize, GEMM_SMEM);
    }

    // Fork: CSR build on s2 runs concurrently with GEMM on the main stream.
    cudaEventRecord(evFork, 0);
    cudaStreamWaitEvent(s2, evFork, 0);

    k_zero_cnt<<<(N + 255) / 256, 256, 0, s2>>>(N);
    k_count<<<(E + 255) / 256, 256, 0, s2>>>(rows, E);
    k_scan<<<1, SCAN_T, 0, s2>>>(N, E);
    k_fill<<<(E + 255) / 256, 256, 0, s2>>>(rows, cols, vals, E);
    cudaEventRecord(evJoin, s2);

    // GEMM: fp16 wmma, BM=128
    int gtiles = (M + 127) / 128;
    gemm_wmma<<<gtiles, 256, GEMM_SMEM>>>(x, W, M, N);

    // Join: gather needs both CSR and z.
    cudaStreamWaitEvent(0, evJoin, 0);
    int blocks = (N * 64 + 255) / 256;
    k_gather<<<blocks, 256>>>(bias, out, N);
}

// round 15
// speedup vs baseline: 1.0025x; 1.0025x over previous
#include <cuda_runtime.h>
#include <cuda_fp16.h>
#include <mma.h>
#include <cstdint>

using namespace nvcuda;

// GraphConvolution: y = A @ (x @ W^T) + b
//   x: (B=4, N=50000, C=128) f32, adj: (2, E=800000) i32, vals: (E,) f32
//   W: (128,128) f32, b: (128,) f32, out: (B,N,128) f32

#define C_DIM 128
#define B_DIM 4
#define N_ROWS 50000
#define E_MAX  800000

// z stored fp16, node-major: z_h[n][b][c] -> 128 uint2 (512 halfs) per node.
__device__ uint2  g_zh[(size_t)N_ROWS * 128];
__device__ int    g_cnt[N_ROWS];
__device__ int    g_rowptr[N_ROWS + 1];
__device__ int    g_ofs[N_ROWS];
__device__ float2 g_edata[E_MAX];

// ===========================================================================
// GEMM z = x @ W^T via wmma fp16 (m16n16k16), fp32 accumulate,
// output fp16 node-major. (exact R13 version — known-good)
// ===========================================================================
#define LDAH 136
#define LDO  132
#define GEMM_SMEM (2 * 128 * LDAH * (int)sizeof(__half))   // 69632 bytes

__global__ __launch_bounds__(256, 2)
void gemm_wmma(const float* __restrict__ x, const float* __restrict__ W,
               int M, int N) {
    extern __shared__ char smemraw[];
    __half* As = (__half*)smemraw;            // [128][LDAH]
    __half* Bs = As + 128 * LDAH;             // [128][LDAH]

    const int tid = threadIdx.x;
    const int wid = tid >> 5;
    const long long m0 = (long long)blockIdx.x * 128;

    #pragma unroll
    for (int it = 0; it < 16; it++) {
        int idx = tid + it * 256;
        int row = idx >> 5;
        int kq  = idx & 31;
        long long gm = m0 + row; if (gm >= M) gm = M - 1;
        float4 v = __ldcs((const float4*)(x + gm * C_DIM + kq * 4));
        __half2 h0 = __floats2half2_rn(v.x, v.y);
        __half2 h1 = __floats2half2_rn(v.z, v.w);
        uint2 p;
        p.x = *(uint32_t*)&h0;
        p.y = *(uint32_t*)&h1;
        *(uint2*)(As + row * LDAH + kq * 4) = p;
    }
    #pragma unroll
    for (int it = 0; it < 16; it++) {
        int idx = tid + it * 256;
        int row = idx >> 5;
        int kq  = idx & 31;
        float4 v = *(const float4*)(W + row * C_DIM + kq * 4);
        __half2 h0 = __floats2half2_rn(v.x, v.y);
        __half2 h1 = __floats2half2_rn(v.z, v.w);
        uint2 p;
        p.x = *(uint32_t*)&h0;
        p.y = *(uint32_t*)&h1;
        *(uint2*)(Bs + row * LDAH + kq * 4) = p;
    }
    __syncthreads();

    const int wm = wid & 1;
    const int wn = wid >> 1;

    wmma::fragment<wmma::accumulator, 16, 16, 16, float> acc[4][2];
    #pragma unroll
    for (int i = 0; i < 4; i++)
        #pragma unroll
        for (int j = 0; j < 2; j++) wmma::fill_fragment(acc[i][j], 0.0f);

    #pragma unroll
    for (int ks = 0; ks < 8; ks++) {
        const int k = ks * 16;
        wmma::fragment<wmma::matrix_a, 16, 16, 16, __half, wmma::row_major> a[4];
        wmma::fragment<wmma::matrix_b, 16, 16, 16, __half, wmma::col_major> b[2];
        #pragma unroll
        for (int i = 0; i < 4; i++)
            wmma::load_matrix_sync(a[i], As + (wm * 64 + i * 16) * LDAH + k, LDAH);
        #pragma unroll
        for (int j = 0; j < 2; j++)
            wmma::load_matrix_sync(b[j], Bs + (wn * 32 + j * 16) * LDAH + k, LDAH);
        #pragma unroll
        for (int i = 0; i < 4; i++)
            #pragma unroll
            for (int j = 0; j < 2; j++)
                wmma::mma_sync(acc[i][j], a[i], b[j], acc[i][j]);
    }

    __syncthreads();
    float* Os = (float*)smemraw;   // 128*132*4 = 67584 <= 69632
    #pragma unroll
    for (int i = 0; i < 4; i++)
        #pragma unroll
        for (int j = 0; j < 2; j++)
            wmma::store_matrix_sync(
                Os + (wm * 64 + i * 16) * LDO + wn * 32 + j * 16,
                acc[i][j], LDO, wmma::mem_row_major);
    __syncthreads();

    #pragma unroll
    for (int it = 0; it < 16; it++) {
        int idx = tid + it * 256;
        int row = idx >> 5;
        int q   = idx & 31;
        long long gm = m0 + row;
        if (gm < M) {
            float4 v = *(const float4*)(Os + row * LDO + q * 4);
            __half2 h0 = __floats2half2_rn(v.x, v.y);
            __half2 h1 = __floats2half2_rn(v.z, v.w);
            int b = (int)(gm / N);
            int n = (int)(gm % N);
            uint2 pack;
            pack.x = *(uint32_t*)&h0;
            pack.y = *(uint32_t*)&h1;
            g_zh[(size_t)n * 128 + b * 32 + q] = pack;
        }
    }
}

// ===========================================================================
// CSR build
// ===========================================================================
__global__ void k_zero_cnt(int n) {
    int i = blockIdx.x * blockDim.x + threadIdx.x;
    if (i < n) g_cnt[i] = 0;
}

__global__ void k_count(const int* __restrict__ rows, int E) {
    int e = blockIdx.x * blockDim.x + threadIdx.x;
    if (e < E) atomicAdd(&g_cnt[rows[e]], 1);
}

#define SCAN_T 1024
__global__ __launch_bounds__(SCAN_T)
void k_scan(int n, int E) {
    __shared__ int s[SCAN_T];
    const int t = threadIdx.x;
    const int chunk = (n + SCAN_T - 1) / SCAN_T;
    const int base = t * chunk;
    int sum = 0;
    for (int j = 0; j < chunk; j++) {
        int r = base + j;
        if (r < n) sum += g_cnt[r];
    }
    s[t] = sum;
    __syncthreads();
    #pragma unroll
    for (int d = 1; d < SCAN_T; d <<= 1) {
        int v = (t >= d) ? s[t - d] : 0;
        __syncthreads();
        s[t] += v;
        __syncthreads();
    }
    int run = s[t] - sum;
    for (int j = 0; j < chunk; j++) {
        int r = base + j;
        if (r < n) {
            g_rowptr[r] = run;
            g_ofs[r]    = run;
            run += g_cnt[r];
        }
    }
    if (t == 0) g_rowptr[n] = E;
}

__global__ void k_fill(const int* __restrict__ rows, const int* __restrict__ cols,
                       const float* __restrict__ vals, int E) {
    int e = blockIdx.x * blockDim.x + threadIdx.x;
    if (e >= E) return;
    int r = rows[e];
    int pos = atomicAdd(&g_ofs[r], 1);
    float2 ed;
    ed.x = __int_as_float(cols[e]);
    ed.y = vals[e];
    g_edata[pos] = ed;
}

// ===========================================================================
// Gather: 2 warps per row (warp covers 2 batches), R9 loop structure, but
// ONE uint4 (16B/lane) load per edge instead of two uint2 loads: warp reads
// the whole 512B half-block in a single LDG.128. Lane owns 8 consecutive
// channels of one batch (lanes 0-15: first batch, 16-31: second).
// fp32 accumulate, bias fused, streaming stores.
// ===========================================================================
__device__ __forceinline__ void accum_u4(uint4 p, float v,
                                         float4& lo, float4& hi) {
    float2 f0 = __half22float2(*(__half2*)&p.x);
    float2 f1 = __half22float2(*(__half2*)&p.y);
    float2 f2 = __half22float2(*(__half2*)&p.z);
    float2 f3 = __half22float2(*(__half2*)&p.w);
    lo.x = fmaf(v, f0.x, lo.x); lo.y = fmaf(v, f0.y, lo.y);
    lo.z = fmaf(v, f1.x, lo.z); lo.w = fmaf(v, f1.y, lo.w);
    hi.x = fmaf(v, f2.x, hi.x); hi.y = fmaf(v, f2.y, hi.y);
    hi.z = fmaf(v, f3.x, hi.z); hi.w = fmaf(v, f3.y, hi.w);
}

__global__ __launch_bounds__(256)
void k_gather(const float* __restrict__ bias, float* __restrict__ out, int N) {
    int gw   = (blockIdx.x * blockDim.x + threadIdx.x) >> 5;
    int lane = threadIdx.x & 31;
    int r    = gw >> 1;
    int half = gw & 1;          // 0: batches {0,1}, 1: batches {2,3}
    if (r >= N) return;

    // uint4 view: node block = 64 uint4; half-block = 32 uint4.
    const uint4* zb = (const uint4*)g_zh;
    const int loff = half * 32 + lane;   // uint4 offset within node block

    float4 acc_lo = make_float4(0.f, 0.f, 0.f, 0.f);
    float4 acc_hi = acc_lo, bcc_lo = acc_lo, bcc_hi = acc_lo;

    const int start = g_rowptr[r];
    const int end   = g_rowptr[r + 1];

    int i = start;
    for (; i + 2 <= end; i += 2) {
        float2 e0 = __ldg(&g_edata[i]);
        float2 e1 = __ldg(&g_edata[i + 1]);
        uint4 p0 = __ldg(zb + (size_t)__float_as_int(e0.x) * 64 + loff);
        uint4 p1 = __ldg(zb + (size_t)__float_as_int(e1.x) * 64 + loff);
        accum_u4(p0, e0.y, acc_lo, acc_hi);
        accum_u4(p1, e1.y, bcc_lo, bcc_hi);
    }
    if (i < end) {
        float2 e0 = __ldg(&g_edata[i]);
        uint4 p0 = __ldg(zb + (size_t)__float_as_int(e0.x) * 64 + loff);
        accum_u4(p0, e0.y, acc_lo, acc_hi);
    }

    // Lane owns channels [ (lane&15)*8, +8 ) of batch half*2 + (lane>>4).
    const int ch8 = (lane & 15) * 2;    // float4 index within row (2 per lane)
    float4 bv0 = ((const float4*)bias)[ch8];
    float4 bv1 = ((const float4*)bias)[ch8 + 1];
    acc_lo.x += bcc_lo.x + bv0.x; acc_lo.y += bcc_lo.y + bv0.y;
    acc_lo.z += bcc_lo.z + bv0.z; acc_lo.w += bcc_lo.w + bv0.w;
    acc_hi.x += bcc_hi.x + bv1.x; acc_hi.y += bcc_hi.y + bv1.y;
    acc_hi.z += bcc_hi.z + bv1.z; acc_hi.w += bcc_hi.w + bv1.w;

    const size_t NB = (size_t)N * 32;   // float4 units per batch
    const int b = half * 2 + (lane >> 4);
    float4* dst = (float4*)out + (size_t)b * NB + (size_t)r * 32 + ch8;
    __stcs(dst,     acc_lo);
    __stcs(dst + 1, acc_hi);
}

// ===========================================================================
extern "C" void kernel_launch(void* const* d_in, const int* in_sizes, int n_in,
                              void* d_out, int out_size) {
    const float* x    = (const float*)d_in[0];
    const int*   adj  = (const int*)d_in[1];
    const float* vals = (const float*)d_in[2];
    const float* W    = (const float*)d_in[3];
    const float* bias = (const float*)d_in[4];
    float* out = (float*)d_out;

    const int E = in_sizes[2];
    const int N = in_sizes[0] / (B_DIM * C_DIM);
    const int M = B_DIM * N;

    const int* rows = adj;
    const int* cols = adj + E;

    static cudaStream_t s2 = nullptr;
    static cudaEvent_t evFork, evJoin;
    if (!s2) {
        cudaStreamCreateWithFlags(&s2, cudaStreamNonBlocking);
        cudaEventCreateWithFlags(&evFork, cudaEventDisableTiming);
        cudaEventCreateWithFlags(&evJoin, cudaEventDisableTiming);
        cudaFuncSetAttribute(gemm_wmma,
                             cudaFuncAttributeMaxDynamicSharedMemorySize, GEMM_SMEM);
    }

    // Fork: CSR build on s2 runs concurrently with GEMM on the main stream.
    cudaEventRecord(evFork, 0);
    cudaStreamWaitEvent(s2, evFork, 0);

    k_zero_cnt<<<(N + 255) / 256, 256, 0, s2>>>(N);
    k_count<<<(E + 255) / 256, 256, 0, s2>>>(rows, E);
    k_scan<<<1, SCAN_T, 0, s2>>>(N, E);
    k_fill<<<(E + 255) / 256, 256, 0, s2>>>(rows, cols, vals, E);
    cudaEventRecord(evJoin, s2);

    // GEMM: fp16 wmma, BM=128
    int gtiles = (M + 127) / 128;
    gemm_wmma<<<gtiles, 256, GEMM_SMEM>>>(x, W, M, N);

    // Join: gather needs both CSR and z.
    cudaStreamWaitEvent(0, evJoin, 0);
    int blocks = (N * 64 + 255) / 256;
    k_gather<<<blocks, 256>>>(bias, out, N);
}

// round 16
// speedup vs baseline: 1.1542x; 1.1513x over previous
#include <cuda_runtime.h>
#include <cuda_fp16.h>
#include <mma.h>
#include <cstdint>

using namespace nvcuda;

// GraphConvolution: y = A @ (x @ W^T) + b
//   x: (B=4, N=50000, C=128) f32, adj: (2, E=800000) i32, vals: (E,) f32
//   W: (128,128) f32, b: (128,) f32, out: (B,N,128) f32

#define C_DIM 128
#define B_DIM 4
#define N_ROWS 50000
#define E_MAX  800000

// z stored fp16, node-major: z_h[n][b][c] -> 128 uint2 (512 halfs) per node.
__device__ uint2  g_zh[(size_t)N_ROWS * 128];
__device__ int    g_cnt[N_ROWS];
__device__ int    g_rowptr[N_ROWS + 1];
__device__ int    g_ofs[N_ROWS];
__device__ float2 g_edata[E_MAX];
__device__ int    g_bar;          // grid barrier counter (zeroed each call)

// ===========================================================================
// GEMM z = x @ W^T via wmma fp16 (m16n16k16), fp32 accumulate,
// output fp16 node-major. (exact R13 version — known-good)
// ===========================================================================
#define LDAH 136
#define LDO  132
#define GEMM_SMEM (2 * 128 * LDAH * (int)sizeof(__half))   // 69632 bytes

__global__ __launch_bounds__(256, 2)
void gemm_wmma(const float* __restrict__ x, const float* __restrict__ W,
               int M, int N) {
    extern __shared__ char smemraw[];
    __half* As = (__half*)smemraw;            // [128][LDAH]
    __half* Bs = As + 128 * LDAH;             // [128][LDAH]

    const int tid = threadIdx.x;
    const int wid = tid >> 5;
    const long long m0 = (long long)blockIdx.x * 128;

    #pragma unroll
    for (int it = 0; it < 16; it++) {
        int idx = tid + it * 256;
        int row = idx >> 5;
        int kq  = idx & 31;
        long long gm = m0 + row; if (gm >= M) gm = M - 1;
        float4 v = __ldcs((const float4*)(x + gm * C_DIM + kq * 4));
        __half2 h0 = __floats2half2_rn(v.x, v.y);
        __half2 h1 = __floats2half2_rn(v.z, v.w);
        uint2 p;
        p.x = *(uint32_t*)&h0;
        p.y = *(uint32_t*)&h1;
        *(uint2*)(As + row * LDAH + kq * 4) = p;
    }
    #pragma unroll
    for (int it = 0; it < 16; it++) {
        int idx = tid + it * 256;
        int row = idx >> 5;
        int kq  = idx & 31;
        float4 v = *(const float4*)(W + row * C_DIM + kq * 4);
        __half2 h0 = __floats2half2_rn(v.x, v.y);
        __half2 h1 = __floats2half2_rn(v.z, v.w);
        uint2 p;
        p.x = *(uint32_t*)&h0;
        p.y = *(uint32_t*)&h1;
        *(uint2*)(Bs + row * LDAH + kq * 4) = p;
    }
    __syncthreads();

    const int wm = wid & 1;
    const int wn = wid >> 1;

    wmma::fragment<wmma::accumulator, 16, 16, 16, float> acc[4][2];
    #pragma unroll
    for (int i = 0; i < 4; i++)
        #pragma unroll
        for (int j = 0; j < 2; j++) wmma::fill_fragment(acc[i][j], 0.0f);

    #pragma unroll
    for (int ks = 0; ks < 8; ks++) {
        const int k = ks * 16;
        wmma::fragment<wmma::matrix_a, 16, 16, 16, __half, wmma::row_major> a[4];
        wmma::fragment<wmma::matrix_b, 16, 16, 16, __half, wmma::col_major> b[2];
        #pragma unroll
        for (int i = 0; i < 4; i++)
            wmma::load_matrix_sync(a[i], As + (wm * 64 + i * 16) * LDAH + k, LDAH);
        #pragma unroll
        for (int j = 0; j < 2; j++)
            wmma::load_matrix_sync(b[j], Bs + (wn * 32 + j * 16) * LDAH + k, LDAH);
        #pragma unroll
        for (int i = 0; i < 4; i++)
            #pragma unroll
            for (int j = 0; j < 2; j++)
                wmma::mma_sync(acc[i][j], a[i], b[j], acc[i][j]);
    }

    __syncthreads();
    float* Os = (float*)smemraw;   // 128*132*4 = 67584 <= 69632
    #pragma unroll
    for (int i = 0; i < 4; i++)
        #pragma unroll
        for (int j = 0; j < 2; j++)
            wmma::store_matrix_sync(
                Os + (wm * 64 + i * 16) * LDO + wn * 32 + j * 16,
                acc[i][j], LDO, wmma::mem_row_major);
    __syncthreads();

    #pragma unroll
    for (int it = 0; it < 16; it++) {
        int idx = tid + it * 256;
        int row = idx >> 5;
        int q   = idx & 31;
        long long gm = m0 + row;
        if (gm < M) {
            float4 v = *(const float4*)(Os + row * LDO + q * 4);
            __half2 h0 = __floats2half2_rn(v.x, v.y);
            __half2 h1 = __floats2half2_rn(v.z, v.w);
            int b = (int)(gm / N);
            int n = (int)(gm % N);
            uint2 pack;
            pack.x = *(uint32_t*)&h0;
            pack.y = *(uint32_t*)&h1;
            g_zh[(size_t)n * 128 + b * 32 + q] = pack;
        }
    }
}

// ===========================================================================
// CSR build: 2 launches.
//  k_zero: zero counts + barrier.
//  k_csr:  count -> grid-bar -> scan (CTA0) -> grid-bar -> fill.
//  Single wave: 120 CTAs x 256 threads (<= SM count, 1 CTA/SM trivially).
// ===========================================================================
#define CSR_CTAS 120
#define CSR_THR  256

__global__ void k_zero(int n) {
    int i = blockIdx.x * blockDim.x + threadIdx.x;
    if (i == 0) g_bar = 0;
    for (; i < n; i += gridDim.x * blockDim.x) g_cnt[i] = 0;
}

__device__ __forceinline__ void grid_bar(int target) {
    __syncthreads();
    if (threadIdx.x == 0) {
        __threadfence();
        atomicAdd(&g_bar, 1);
        while (atomicAdd(&g_bar, 0) < target) __nanosleep(64);
    }
    __syncthreads();
}

__global__ __launch_bounds__(CSR_THR)
void k_csr(const int* __restrict__ rows, const int* __restrict__ cols,
           const float* __restrict__ vals, int E, int n) {
    const int tid  = blockIdx.x * blockDim.x + threadIdx.x;
    const int nthr = gridDim.x * blockDim.x;

    // Phase 1: count
    for (int e = tid; e < E; e += nthr)
        atomicAdd(&g_cnt[rows[e]], 1);

    grid_bar(CSR_CTAS);

    // Phase 2: scan (CTA 0 only, 256 threads, chunked serial + block scan)
    if (blockIdx.x == 0) {
        __shared__ int s[CSR_THR];
        const int t = threadIdx.x;
        const int chunk = (n + CSR_THR - 1) / CSR_THR;
        const int base = t * chunk;
        int sum = 0;
        for (int j = 0; j < chunk; j++) {
            int r = base + j;
            if (r < n) sum += g_cnt[r];
        }
        s[t] = sum;
        __syncthreads();
        #pragma unroll
        for (int d = 1; d < CSR_THR; d <<= 1) {
            int v = (t >= d) ? s[t - d] : 0;
            __syncthreads();
            s[t] += v;
            __syncthreads();
        }
        int run = s[t] - sum;   // exclusive prefix
        for (int j = 0; j < chunk; j++) {
            int r = base + j;
            if (r < n) {
                g_rowptr[r] = run;
                g_ofs[r]    = run;
                run += g_cnt[r];
            }
        }
        if (t == 0) g_rowptr[n] = E;
        __threadfence();
    }

    grid_bar(2 * CSR_CTAS);

    // Phase 3: fill
    for (int e = tid; e < E; e += nthr) {
        int r = rows[e];
        int pos = atomicAdd(&g_ofs[r], 1);
        float2 ed;
        ed.x = __int_as_float(cols[e]);
        ed.y = vals[e];
        g_edata[pos] = ed;
    }
}

// ===========================================================================
// Gather (exact R13/R9 version — best known): 2 warps per row, warp covers
// 2 batches, 2-way unrolled, fp32 accumulate, bias fused, streaming stores.
// ===========================================================================
__device__ __forceinline__ void accum_pair(const uint2* __restrict__ src,
                                           int lane, float v,
                                           float4& a0, float4& a1) {
    uint2 p0 = __ldg(src + lane);
    uint2 p1 = __ldg(src + lane + 32);
    float2 fa, fb;
    fa = __half22float2(*(__half2*)&p0.x); fb = __half22float2(*(__half2*)&p0.y);
    a0.x = fmaf(v, fa.x, a0.x); a0.y = fmaf(v, fa.y, a0.y);
    a0.z = fmaf(v, fb.x, a0.z); a0.w = fmaf(v, fb.y, a0.w);
    fa = __half22float2(*(__half2*)&p1.x); fb = __half22float2(*(__half2*)&p1.y);
    a1.x = fmaf(v, fa.x, a1.x); a1.y = fmaf(v, fa.y, a1.y);
    a1.z = fmaf(v, fb.x, a1.z); a1.w = fmaf(v, fb.y, a1.w);
}

__global__ __launch_bounds__(256)
void k_gather(const float* __restrict__ bias, float* __restrict__ out, int N) {
    int gw   = (blockIdx.x * blockDim.x + threadIdx.x) >> 5;
    int lane = threadIdx.x & 31;
    int r    = gw >> 1;
    int half = gw & 1;          // 0: batches {0,1}, 1: batches {2,3}
    if (r >= N) return;
    const int boff = half * 64; // uint2 offset into node block

    float4 acc0 = make_float4(0.f, 0.f, 0.f, 0.f);
    float4 acc1 = acc0, bcc0 = acc0, bcc1 = acc0;

    const int start = g_rowptr[r];
    const int end   = g_rowptr[r + 1];

    int i = start;
    for (; i + 2 <= end; i += 2) {
        float2 e0 = __ldg(&g_edata[i]);
        float2 e1 = __ldg(&g_edata[i + 1]);
        const uint2* s0 = g_zh + (size_t)__float_as_int(e0.x) * 128 + boff;
        const uint2* s1 = g_zh + (size_t)__float_as_int(e1.x) * 128 + boff;
        accum_pair(s0, lane, e0.y, acc0, acc1);
        accum_pair(s1, lane, e1.y, bcc0, bcc1);
    }
    if (i < end) {
        float2 e0 = __ldg(&g_edata[i]);
        const uint2* s0 = g_zh + (size_t)__float_as_int(e0.x) * 128 + boff;
        accum_pair(s0, lane, e0.y, acc0, acc1);
    }

    float4 bv = ((const float4*)bias)[lane];
    acc0.x += bcc0.x + bv.x; acc0.y += bcc0.y + bv.y;
    acc0.z += bcc0.z + bv.z; acc0.w += bcc0.w + bv.w;
    acc1.x += bcc1.x + bv.x; acc1.y += bcc1.y + bv.y;
    acc1.z += bcc1.z + bv.z; acc1.w += bcc1.w + bv.w;

    const size_t NB = (size_t)N * 32;   // float4 units per batch
    float4* dst = (float4*)out + (size_t)(half * 2) * NB + (size_t)r * 32 + lane;
    __stcs(dst,      acc0);
    __stcs(dst + NB, acc1);
}

// ===========================================================================
extern "C" void kernel_launch(void* const* d_in, const int* in_sizes, int n_in,
                              void* d_out, int out_size) {
    const float* x    = (const float*)d_in[0];
    const int*   adj  = (const int*)d_in[1];
    const float* vals = (const float*)d_in[2];
    const float* W    = (const float*)d_in[3];
    const float* bias = (const float*)d_in[4];
    float* out = (float*)d_out;

    const int E = in_sizes[2];
    const int N = in_sizes[0] / (B_DIM * C_DIM);
    const int M = B_DIM * N;

    const int* rows = adj;
    const int* cols = adj + E;

    static cudaStream_t s2 = nullptr;
    static cudaEvent_t evFork, evJoin;
    if (!s2) {
        cudaStreamCreateWithFlags(&s2, cudaStreamNonBlocking);
        cudaEventCreateWithFlags(&evFork, cudaEventDisableTiming);
        cudaEventCreateWithFlags(&evJoin, cudaEventDisableTiming);
        cudaFuncSetAttribute(gemm_wmma,
                             cudaFuncAttributeMaxDynamicSharedMemorySize, GEMM_SMEM);
    }

    // Fork: CSR build on s2 runs concurrently with GEMM on the main stream.
    cudaEventRecord(evFork, 0);
    cudaStreamWaitEvent(s2, evFork, 0);

    k_zero<<<64, 256, 0, s2>>>(N);
    k_csr<<<CSR_CTAS, CSR_THR, 0, s2>>>(rows, cols, vals, E, N);
    cudaEventRecord(evJoin, s2);

    // GEMM: fp16 wmma, BM=128
    int gtiles = (M + 127) / 128;
    gemm_wmma<<<gtiles, 256, GEMM_SMEM>>>(x, W, M, N);

    // Join: gather needs both CSR and z.
    cudaStreamWaitEvent(0, evJoin, 0);
    int blocks = (N * 64 + 255) / 256;
    k_gather<<<blocks, 256>>>(bias, out, N);
}